// round 9
// baseline (speedup 1.0000x reference)
#include <cuda_runtime.h>
#include <cuda_fp16.h>
#include <cstdint>
#include <math.h>

#define B_  2
#define T_  2048
#define C_  768
#define H_  12
#define HD_ 64
#define M_  (B_*T_)   // 4096

// Scratch (allocations forbidden -> device globals)
__device__ __half g_hx[M_*C_];
__device__ __half g_hq[M_*C_];
__device__ __half g_hk[M_*C_];
__device__ __half g_hv[M_*C_];
__device__ __half g_hy[M_*C_];
__device__ __half g_hwq[C_*C_];
__device__ __half g_hwk[C_*C_];
__device__ __half g_hwv[C_*C_];
__device__ __half g_hwp[C_*C_];

// ---------------------------------------------------------------------------
__device__ __forceinline__ uint32_t smem_u32(const void* p) {
    uint32_t r;
    asm("{ .reg .u64 t; cvta.to.shared.u64 t, %1; cvt.u32.u64 %0, t; }"
        : "=r"(r) : "l"(p));
    return r;
}
__device__ __forceinline__ void cp16(uint32_t dst, const void* src) {
    asm volatile("cp.async.ca.shared.global [%0], [%1], 16;" :: "r"(dst), "l"(src));
}
#define CP_COMMIT() asm volatile("cp.async.commit_group;" ::: "memory")
#define CP_WAIT(N)  asm volatile("cp.async.wait_group %0;" :: "n"(N) : "memory")

__device__ __forceinline__ void ldm4(uint32_t r[4], uint32_t a) {
    asm volatile("ldmatrix.sync.aligned.m8n8.x4.shared.b16 {%0,%1,%2,%3}, [%4];"
        : "=r"(r[0]), "=r"(r[1]), "=r"(r[2]), "=r"(r[3]) : "r"(a));
}
__device__ __forceinline__ void ldm4t(uint32_t r[4], uint32_t a) {
    asm volatile("ldmatrix.sync.aligned.m8n8.x4.trans.shared.b16 {%0,%1,%2,%3}, [%4];"
        : "=r"(r[0]), "=r"(r[1]), "=r"(r[2]), "=r"(r[3]) : "r"(a));
}
__device__ __forceinline__ void mma_f16(float d[4], const uint32_t a[4], const uint32_t b[2]) {
    asm volatile(
        "mma.sync.aligned.m16n8k16.row.col.f32.f16.f16.f32 "
        "{%0,%1,%2,%3}, {%4,%5,%6,%7}, {%8,%9}, {%0,%1,%2,%3};"
        : "+f"(d[0]), "+f"(d[1]), "+f"(d[2]), "+f"(d[3])
        : "r"(a[0]), "r"(a[1]), "r"(a[2]), "r"(a[3]), "r"(b[0]), "r"(b[1]));
}
__device__ __forceinline__ uint32_t pack_h2(float p0, float p1) {
    uint32_t u;
    asm("cvt.rn.f16x2.f32 %0, %1, %2;" : "=r"(u) : "f"(p1), "f"(p0));
    return u;
}

// ---------------------------------------------------------------------------
// fused f32 -> f16 convert: x + 4 weight matrices in ONE launch
// ---------------------------------------------------------------------------
#define X4_ (M_*C_/4)
#define W4_ (C_*C_/4)
#define N4TOT_ (X4_ + 4*W4_)

__global__ void f2h5(const float* __restrict__ x,
                     const float* __restrict__ w0, const float* __restrict__ w1,
                     const float* __restrict__ w2, const float* __restrict__ w3)
{
    int i = blockIdx.x * blockDim.x + threadIdx.x;
    if (i >= N4TOT_) return;
    const float* s;
    __half* d;
    int k;
    if (i < X4_) { s = x; d = g_hx; k = i; }
    else {
        int j = i - X4_;
        int seg = j / W4_;
        k = j - seg * W4_;
        s = (seg == 0) ? w0 : (seg == 1) ? w1 : (seg == 2) ? w2 : w3;
        d = (seg == 0) ? g_hwq : (seg == 1) ? g_hwk : (seg == 2) ? g_hwv : g_hwp;
    }
    float4 v = ((const float4*)s)[k];
    ((__half2*)d)[2 * k + 0] = __floats2half2_rn(v.x, v.y);
    ((__half2*)d)[2 * k + 1] = __floats2half2_rn(v.z, v.w);
}

// ===========================================================================
// fp16 mma.sync GEMM: C = A @ W^T + bias. CTA 256x128, BK=64, 8 warps (4x2),
// warp tile 64x64. ldmatrix fragments, 3-stage cp.async, 1 sync/chunk,
// direct-gmem epilogue.
// ===========================================================================
#define LDGH 72                       // halfs per smem row (144B) - conflict-free
#define NCH  12                       // 768/64

#define G_A_SZ (256*LDGH*2)           // 36864
#define G_W_SZ (128*LDGH*2)           // 18432
#define G_BUF  (G_A_SZ + G_W_SZ)      // 55296
#define SMEM_GEMM_ (3*G_BUF)          // 165888

__global__ __launch_bounds__(256) void gemm_m(
    const __half* __restrict__ A,
    const __half* __restrict__ W0, const __half* __restrict__ W1, const __half* __restrict__ W2,
    const float* __restrict__ b0, const float* __restrict__ b1, const float* __restrict__ b2,
    __half* __restrict__ C0, __half* __restrict__ C1, __half* __restrict__ C2,
    float* __restrict__ CF)
{
    extern __shared__ char smc[];
    const uint32_t sb = smem_u32(smc);

    const int tid  = threadIdx.x;
    const int wid  = tid >> 5;
    const int lane = tid & 31;
    const int q4   = lane & 3;
    const int rr   = lane >> 2;
    const int lrow = lane & 15;
    const int lc8  = (lane >> 4) * 8;
    const int warp_m = wid & 3;       // 64-row group
    const int warp_n = wid >> 2;      // 64-col group

    const int m0 = blockIdx.x * 256;
    const int which = blockIdx.y / 6;
    const int n0 = (blockIdx.y % 6) * 128;
    const __half* W   = (which == 0) ? W0 : (which == 1) ? W1 : W2;
    const float* bias = (which == 0) ? b0 : (which == 1) ? b1 : b2;
    __half*      Cm   = (which == 0) ? C0 : (which == 1) ? C1 : C2;

    const __half* Arow = A + (size_t)m0 * C_;
    const __half* Wrow = W + (size_t)n0 * C_;

    float acc[4][8][4];
    #pragma unroll
    for (int mb = 0; mb < 4; mb++)
        #pragma unroll
        for (int nb = 0; nb < 8; nb++)
            #pragma unroll
            for (int e = 0; e < 4; e++)
                acc[mb][nb][e] = 0.0f;

    auto stage = [&](int buf, int k0) {
        uint32_t Ad = sb + (uint32_t)buf * G_BUF;
        uint32_t Wd = Ad + (uint32_t)G_A_SZ;
        #pragma unroll
        for (int e = 0; e < 8; e++) {                 // A: 256 rows x 8 chunks
            int lin = e * 256 + tid;
            int row = lin >> 3, c8 = lin & 7;
            cp16(Ad + (uint32_t)(row * LDGH + c8 * 8) * 2,
                 Arow + (size_t)row * C_ + k0 + c8 * 8);
        }
        #pragma unroll
        for (int e = 0; e < 4; e++) {                 // W: 128 rows x 8 chunks
            int lin = e * 256 + tid;
            int row = lin >> 3, c8 = lin & 7;
            cp16(Wd + (uint32_t)(row * LDGH + c8 * 8) * 2,
                 Wrow + (size_t)row * C_ + k0 + c8 * 8);
        }
    };

    stage(0, 0);  CP_COMMIT();
    stage(1, 64); CP_COMMIT();

    for (int c = 0; c < NCH; c++) {
        if (c < NCH - 1) { CP_WAIT(1); } else { CP_WAIT(0); }
        __syncthreads();
        if (c + 2 < NCH) { stage((c + 2) % 3, (c + 2) * 64); CP_COMMIT(); }

        uint32_t Ab = sb + (uint32_t)(c % 3) * G_BUF;
        uint32_t Wb = Ab + (uint32_t)G_A_SZ;
        #pragma unroll
        for (int ks = 0; ks < 4; ks++) {
            uint32_t af[4][4];
            #pragma unroll
            for (int mb = 0; mb < 4; mb++)
                ldm4(af[mb], Ab + (uint32_t)((warp_m * 64 + mb * 16 + lrow) * LDGH
                                             + ks * 16 + lc8) * 2);
            #pragma unroll
            for (int jj = 0; jj < 4; jj++) {
                uint32_t wr[4];
                ldm4(wr, Wb + (uint32_t)((warp_n * 64 + jj * 16 + lrow) * LDGH
                                         + ks * 16 + lc8) * 2);
                uint32_t bA[2] = { wr[0], wr[2] };
                uint32_t bB[2] = { wr[1], wr[3] };
                #pragma unroll
                for (int mb = 0; mb < 4; mb++) {
                    mma_f16(acc[mb][2 * jj + 0], af[mb], bA);
                    mma_f16(acc[mb][2 * jj + 1], af[mb], bB);
                }
            }
        }
    }

    // ---- direct-gmem epilogue with bias ----
    #pragma unroll
    for (int mb = 0; mb < 4; mb++) {
        size_t gr = (size_t)(m0 + warp_m * 64 + mb * 16 + rr);
        #pragma unroll
        for (int nb = 0; nb < 8; nb++) {
            int gc = n0 + warp_n * 64 + nb * 8 + 2 * q4;
            float bb0 = bias[gc], bb1 = bias[gc + 1];
            if (CF) {
                float2 v0 = { acc[mb][nb][0] + bb0, acc[mb][nb][1] + bb1 };
                float2 v1 = { acc[mb][nb][2] + bb0, acc[mb][nb][3] + bb1 };
                *(float2*)(CF + gr * C_ + gc)       = v0;
                *(float2*)(CF + (gr + 8) * C_ + gc) = v1;
            } else {
                *(__half2*)(Cm + gr * C_ + gc) =
                    __floats2half2_rn(acc[mb][nb][0] + bb0, acc[mb][nb][1] + bb1);
                *(__half2*)(Cm + (gr + 8) * C_ + gc) =
                    __floats2half2_rn(acc[mb][nb][2] + bb0, acc[mb][nb][3] + bb1);
            }
        }
    }
}

// ===========================================================================
// mma.sync attention, 128 q-rows per CTA (two 64-row q-blocks share the K/V
// stream -> half the L2 traffic). 4 warps / 128 threads. S,P,O in registers.
// V fragments loaded once per tile, used by both q-blocks.
// ===========================================================================
#define KLD 72
#define NT  32

#define AOF_K0 0
#define AOF_K1 (64*KLD*2)                   //  9216
#define AOF_V0 (2*64*KLD*2)                 // 18432
#define AOF_V1 (3*64*KLD*2)                 // 27648
#define AOF_Q  (4*64*KLD*2)                 // 36864
#define AOF_MD (AOF_Q + 128*KLD*2)          // 55296
#define ATTN_SMEM (AOF_MD + 2*64*4)         // 55808

__global__ __launch_bounds__(128) void attn_m(const int* __restrict__ mask)
{
    extern __shared__ char smc[];
    const uint32_t sb = smem_u32(smc);

    const int tid  = threadIdx.x;
    const int w    = tid >> 5;
    const int lane = tid & 31;
    const int q4   = lane & 3;
    const int lrow = lane & 15;
    const int lc8  = (lane >> 4) * 8;

    const int t0 = blockIdx.x * 128;
    const int h  = blockIdx.y;
    const int b  = blockIdx.z;

    const __half* Qg = g_hq + (size_t)b * T_ * C_ + h * HD_;
    const __half* Kg = g_hk + (size_t)b * T_ * C_ + h * HD_;
    const __half* Vg = g_hv + (size_t)b * T_ * C_ + h * HD_;
    const int*    Mg = mask + b * T_;

    auto stageKV = [&](int buf, int kt) {
        int k0 = kt * 64;
        uint32_t Kd = sb + (buf ? AOF_K1 : AOF_K0);
        uint32_t Vd = sb + (buf ? AOF_V1 : AOF_V0);
        #pragma unroll
        for (int e = 0; e < 4; e++) {
            int lin = e * 128 + tid;
            int row = lin >> 3, c8 = lin & 7;
            uint32_t off = (uint32_t)(row * KLD + c8 * 8) * 2;
            cp16(Kd + off, Kg + (size_t)(k0 + row) * C_ + c8 * 8);
            cp16(Vd + off, Vg + (size_t)(k0 + row) * C_ + c8 * 8);
        }
        if (tid < 16)
            cp16(sb + (uint32_t)(AOF_MD + buf * 256 + tid * 16), Mg + k0 + tid * 4);
    };

    // prologue: 128 Q rows + first K/V tile + mask
    #pragma unroll
    for (int e = 0; e < 8; e++) {
        int lin = e * 128 + tid;
        int row = lin >> 3, c8 = lin & 7;
        cp16(sb + AOF_Q + (uint32_t)(row * KLD + c8 * 8) * 2,
             Qg + (size_t)(t0 + row) * C_ + c8 * 8);
    }
    stageKV(0, 0);
    CP_COMMIT();
    CP_WAIT(0);
    __syncthreads();

    // Q fragments: block g covers rows g*64 + w*16 .. +15
    uint32_t qa[2][4][4];
    #pragma unroll
    for (int g = 0; g < 2; g++)
        #pragma unroll
        for (int c = 0; c < 4; c++)
            ldm4(qa[g][c], sb + AOF_Q +
                 (uint32_t)((g * 64 + w * 16 + lrow) * KLD + c * 16 + lc8) * 2);

    float oacc[2][8][4];
    #pragma unroll
    for (int g = 0; g < 2; g++)
        #pragma unroll
        for (int nb = 0; nb < 8; nb++)
            #pragma unroll
            for (int e = 0; e < 4; e++)
                oacc[g][nb][e] = 0.0f;

    float lsum[2][2] = {{0.0f, 0.0f}, {0.0f, 0.0f}};

    for (int kt = 0; kt < NT; kt++) {
        const int bb = kt & 1;
        if (kt + 1 < NT) { stageKV(bb ^ 1, kt + 1); CP_COMMIT(); }

        // mask -> registers once per tile (shared by both q-blocks)
        const int* mdp = (const int*)(smc + AOF_MD) + bb * 64;
        float mreg[8][2];
        #pragma unroll
        for (int nb = 0; nb < 8; nb++) {
            int col = nb * 8 + 2 * q4;
            mreg[nb][0] = mdp[col]     ? 0.0f : -1e30f;
            mreg[nb][1] = mdp[col + 1] ? 0.0f : -1e30f;
        }

        uint32_t kbase = sb + (bb ? AOF_K1 : AOF_K0);
        uint32_t vbase = sb + (bb ? AOF_V1 : AOF_V0);

        uint32_t pa[2][4][4];
        #pragma unroll
        for (int g = 0; g < 2; g++) {
            // ---- S_g = Q_g K^T ----
            float sacc[8][4];
            #pragma unroll
            for (int nb = 0; nb < 8; nb++)
                #pragma unroll
                for (int e = 0; e < 4; e++)
                    sacc[nb][e] = 0.0f;
            #pragma unroll
            for (int c = 0; c < 4; c++) {
                #pragma unroll
                for (int j = 0; j < 4; j++) {
                    uint32_t kr[4];
                    ldm4(kr, kbase + (uint32_t)((16 * j + lrow) * KLD + c * 16 + lc8) * 2);
                    uint32_t bA[2] = { kr[0], kr[2] };
                    uint32_t bB[2] = { kr[1], kr[3] };
                    mma_f16(sacc[2 * j + 0], qa[g][c], bA);
                    mma_f16(sacc[2 * j + 1], qa[g][c], bB);
                }
            }
            // ---- P_g = mask*exp(S/8), packed as A-operand frags ----
            #pragma unroll
            for (int j = 0; j < 4; j++) {
                #pragma unroll
                for (int sub = 0; sub < 2; sub++) {
                    int nb = 2 * j + sub;
                    float p0 = __expf(fmaf(sacc[nb][0], 0.125f, mreg[nb][0]));
                    float p1 = __expf(fmaf(sacc[nb][1], 0.125f, mreg[nb][1]));
                    float p2 = __expf(fmaf(sacc[nb][2], 0.125f, mreg[nb][0]));
                    float p3 = __expf(fmaf(sacc[nb][3], 0.125f, mreg[nb][1]));
                    lsum[g][0] += p0 + p1;
                    lsum[g][1] += p2 + p3;
                    pa[g][j][2 * sub + 0] = pack_h2(p0, p1);
                    pa[g][j][2 * sub + 1] = pack_h2(p2, p3);
                }
            }
        }

        // ---- O_g += P_g V : V frags loaded ONCE, used by both blocks ----
        #pragma unroll
        for (int j = 0; j < 4; j++) {
            #pragma unroll
            for (int np = 0; np < 4; np++) {
                uint32_t vr[4];
                ldm4t(vr, vbase + (uint32_t)((16 * j + lrow) * KLD + np * 16 + lc8) * 2);
                uint32_t bA[2] = { vr[0], vr[1] };
                uint32_t bB[2] = { vr[2], vr[3] };
                mma_f16(oacc[0][2 * np + 0], pa[0][j], bA);
                mma_f16(oacc[0][2 * np + 1], pa[0][j], bB);
                mma_f16(oacc[1][2 * np + 0], pa[1][j], bA);
                mma_f16(oacc[1][2 * np + 1], pa[1][j], bB);
            }
        }

        if (kt + 1 < NT) CP_WAIT(0);
        __syncthreads();
    }

    // ---- epilogue: row-quad sums, y = O / l ----
    __half* Yb = g_hy + (size_t)b * T_ * C_ + h * HD_;
    #pragma unroll
    for (int g = 0; g < 2; g++) {
        float l0 = lsum[g][0], l1 = lsum[g][1];
        l0 += __shfl_xor_sync(0xffffffffu, l0, 1);
        l0 += __shfl_xor_sync(0xffffffffu, l0, 2);
        l1 += __shfl_xor_sync(0xffffffffu, l1, 1);
        l1 += __shfl_xor_sync(0xffffffffu, l1, 2);
        float r0 = 1.0f / l0;
        float r1 = 1.0f / l1;
        const int row0 = t0 + g * 64 + w * 16 + (lane >> 2);
        #pragma unroll
        for (int nb = 0; nb < 8; nb++) {
            int col = nb * 8 + 2 * q4;
            *(__half2*)(Yb + (size_t)row0 * C_ + col) =
                __floats2half2_rn(oacc[g][nb][0] * r0, oacc[g][nb][1] * r0);
            *(__half2*)(Yb + (size_t)(row0 + 8) * C_ + col) =
                __floats2half2_rn(oacc[g][nb][2] * r1, oacc[g][nb][3] * r1);
        }
    }
}

// ---------------------------------------------------------------------------
extern "C" void kernel_launch(void* const* d_in, const int* in_sizes, int n_in,
                              void* d_out, int out_size)
{
    const float* x    = (const float*)d_in[0];
    const int*   mask = (const int*)  d_in[1];
    const float* Wq   = (const float*)d_in[2];
    const float* bq   = (const float*)d_in[3];
    const float* Wk   = (const float*)d_in[4];
    const float* bk   = (const float*)d_in[5];
    const float* Wv   = (const float*)d_in[6];
    const float* bv   = (const float*)d_in[7];
    const float* Wp   = (const float*)d_in[8];
    const float* bp   = (const float*)d_in[9];
    float* out = (float*)d_out;

    __half *hx, *hq, *hk, *hv, *hy, *hwq, *hwk, *hwv, *hwp;
    cudaGetSymbolAddress((void**)&hx,  g_hx);
    cudaGetSymbolAddress((void**)&hq,  g_hq);
    cudaGetSymbolAddress((void**)&hk,  g_hk);
    cudaGetSymbolAddress((void**)&hv,  g_hv);
    cudaGetSymbolAddress((void**)&hy,  g_hy);
    cudaGetSymbolAddress((void**)&hwq, g_hwq);
    cudaGetSymbolAddress((void**)&hwk, g_hwk);
    cudaGetSymbolAddress((void**)&hwv, g_hwv);
    cudaGetSymbolAddress((void**)&hwp, g_hwp);

    cudaFuncSetAttribute(gemm_m, cudaFuncAttributeMaxDynamicSharedMemorySize, SMEM_GEMM_);
    cudaFuncSetAttribute(attn_m, cudaFuncAttributeMaxDynamicSharedMemorySize, ATTN_SMEM);

    f2h5<<<(N4TOT_ + 255) / 256, 256>>>(x, Wq, Wk, Wv, Wp);

    gemm_m<<<dim3(M_ / 256, 18), 256, SMEM_GEMM_>>>(
        hx, hwq, hwk, hwv, bq, bk, bv, hq, hk, hv, nullptr);

    attn_m<<<dim3(T_ / 128, H_, B_), 128, ATTN_SMEM>>>(mask);

    gemm_m<<<dim3(M_ / 256, 6), 256, SMEM_GEMM_>>>(
        hy, hwp, hwp, hwp, bp, bp, bp, nullptr, nullptr, nullptr, out);
}